// round 14
// baseline (speedup 1.0000x reference)
#include <cuda_runtime.h>
#include <cstdint>

// ---------------------------------------------------------------------------
// B=1, T=262144, D=8, H=64, A=4
//   mask = any(x != 0, -1); h1 = tanh(x@W1+b1); h2 = tanh(h1@W2+b2)
//   xz = h2@Wx + b_rnn;  h_t = mask ? tanh(xz_t + h_{t-1}@Wh) : h_{t-1}
//   means = hs@Wm + bm
// Inputs: x, W1, b1, W2, b2, Wx, Wh, b_rnn, Wm, bm.  Output: means [T,4] f32.
//
// R8-R13: warm-start chunked scan, single-warp scan CTA, branch-free step.
// R14: (a) scan L=128/W=64 — same total steps, 2x warps/SM for issue packing;
//      (b) encoder f32x2 on layers 2/3 ONLY (layer 1 stays scalar — that was
//      the R10 spill source); layer-3 weights/bias CSCALE-prescaled, pairs
//      stored directly.
//
// CSCALE = -2*log2(e) folded into xz (encoder) and Wh (scan):
// tanh(s) = 2*rcp(ex2(CSCALE*s)+1) - 1; masked blend = one FMA:
// h' = fma(2m, r, h - m*(1+h)).
// ---------------------------------------------------------------------------

#define MAX_T 262144
#define H 64
#define CSCALE (-2.8853900817779268f)   /* -2*log2(e) */

#define CHUNK_L 128     /* output steps per chunk  */
#define WARMUP  64      /* warm-up steps per chunk */
#define PF 4            /* z/mask prefetch depth   */

__device__ float g_xz[MAX_T * H];    // holds CSCALE * (h2@Wx + b_rnn)
__device__ float g_mask[MAX_T];
__device__ float g_hs[MAX_T * H];

// Accurate fast tanh: e = exp(-2|v|); tanh = (1-e)/(1+e), signed.
__device__ __forceinline__ float tanh_fast(float v) {
    float a = fabsf(v) * CSCALE;
    float e;
    asm("ex2.approx.f32 %0, %1;" : "=f"(e) : "f"(a));
    float r;
    asm("rcp.approx.f32 %0, %1;" : "=f"(r) : "f"(e + 1.0f));
    return copysignf((1.0f - e) * r, v);
}

#define FFMA2(d, a, b, c) \
    asm("fma.rn.f32x2 %0, %1, %2, %3;" : "=l"(d) : "l"(a), "l"(b), "l"(c))
#define FMUL2(d, a, b) \
    asm("mul.rn.f32x2 %0, %1, %2;" : "=l"(d) : "l"(a), "l"(b))
#define FADD2(d, a, b) \
    asm("add.rn.f32x2 %0, %1, %2;" : "=l"(d) : "l"(a), "l"(b))
#define PACK2(d, lo, hi) \
    asm("mov.b64 %0, {%1, %2};" : "=l"(d) : "f"(lo), "f"(hi))
#define UNPACK2(lo, hi, s) \
    asm("mov.b64 {%0, %1}, %2;" : "=f"(lo), "=f"(hi) : "l"(s))

// ---------------------------------------------------------------------------
// Kernel 1: encoder. Layer 1 scalar (R9 form). Layers 2/3 f32x2:
// quarter-width u64 pair accumulators (same reg count as R9's float4s),
// weights streamed as ulonglong2, one (h,h) PACK per k (ALU pipe).
// Layer 3: sWx/sbr CSCALE-prescaled at load; acc pairs stored directly.
// ---------------------------------------------------------------------------
__global__ void __launch_bounds__(128, 3) encoder_kernel(
    const float* __restrict__ x,
    const float* __restrict__ W1, const float* __restrict__ b1,
    const float* __restrict__ W2, const float* __restrict__ b2,
    const float* __restrict__ Wx, const float* __restrict__ brnn,
    int T)
{
    __shared__ __align__(16) float sW1[8 * 64];
    __shared__ __align__(16) float sW2[64 * 64];
    __shared__ __align__(16) float sWx[64 * 64];   // CSCALE-prescaled
    __shared__ __align__(16) float sb1[64];
    __shared__ __align__(16) float sb2[64];
    __shared__ __align__(16) float sbr[64];        // CSCALE-prescaled

    for (int i = threadIdx.x; i < 8 * 64; i += 128) sW1[i] = W1[i];
    for (int i = threadIdx.x; i < 64 * 64; i += 128) {
        sW2[i] = W2[i];
        sWx[i] = CSCALE * Wx[i];
    }
    if (threadIdx.x < 64) {
        sb1[threadIdx.x] = b1[threadIdx.x];
        sb2[threadIdx.x] = b2[threadIdx.x];
        sbr[threadIdx.x] = CSCALE * brnn[threadIdx.x];
    }
    __syncthreads();

    const float4* sW1v = (const float4*)sW1;
    const unsigned long long* sb2p = (const unsigned long long*)sb2;
    const unsigned long long* sbrp = (const unsigned long long*)sbr;

    for (long t = (long)blockIdx.x * 128 + threadIdx.x; t < T;
         t += (long)gridDim.x * 128) {
        float4 xa = ((const float4*)x)[t * 2];
        float4 xb = ((const float4*)x)[t * 2 + 1];
        float xv[8] = {xa.x, xa.y, xa.z, xa.w, xb.x, xb.y, xb.z, xb.w};

        bool nz = (xa.x != 0.f) | (xa.y != 0.f) | (xa.z != 0.f) | (xa.w != 0.f) |
                  (xb.x != 0.f) | (xb.y != 0.f) | (xb.z != 0.f) | (xb.w != 0.f);
        g_mask[t] = nz ? 1.0f : 0.0f;

        // ---- h1 = tanh(x @ W1 + b1): scalar (unchanged from R9) ----
        float h1[64];
        {
            float4 acc[16];
            #pragma unroll
            for (int q = 0; q < 16; q++) acc[q] = ((const float4*)sb1)[q];
            #pragma unroll
            for (int d = 0; d < 8; d++) {
                float xd = xv[d];
                #pragma unroll
                for (int q = 0; q < 16; q++) {
                    float4 w = sW1v[d * 16 + q];
                    acc[q].x = fmaf(xd, w.x, acc[q].x);
                    acc[q].y = fmaf(xd, w.y, acc[q].y);
                    acc[q].z = fmaf(xd, w.z, acc[q].z);
                    acc[q].w = fmaf(xd, w.w, acc[q].w);
                }
            }
            #pragma unroll
            for (int q = 0; q < 16; q++) {
                h1[4 * q + 0] = tanh_fast(acc[q].x);
                h1[4 * q + 1] = tanh_fast(acc[q].y);
                h1[4 * q + 2] = tanh_fast(acc[q].z);
                h1[4 * q + 3] = tanh_fast(acc[q].w);
            }
        }

        // ---- h2 = tanh(h1 @ W2 + b2): f32x2, four 16-output quarters ----
        float h2[64];
        #pragma unroll
        for (int qt = 0; qt < 4; qt++) {
            unsigned long long acc[8];
            #pragma unroll
            for (int q = 0; q < 8; q++) acc[q] = sb2p[qt * 8 + q];
            #pragma unroll
            for (int k = 0; k < 64; k++) {
                unsigned long long hk2;
                PACK2(hk2, h1[k], h1[k]);
                const ulonglong2* wr =
                    (const ulonglong2*)(sW2 + k * 64 + qt * 16);
                ulonglong2 wa = wr[0];
                FFMA2(acc[0], hk2, wa.x, acc[0]);
                FFMA2(acc[1], hk2, wa.y, acc[1]);
                ulonglong2 wb = wr[1];
                FFMA2(acc[2], hk2, wb.x, acc[2]);
                FFMA2(acc[3], hk2, wb.y, acc[3]);
                ulonglong2 wc = wr[2];
                FFMA2(acc[4], hk2, wc.x, acc[4]);
                FFMA2(acc[5], hk2, wc.y, acc[5]);
                ulonglong2 wd = wr[3];
                FFMA2(acc[6], hk2, wd.x, acc[6]);
                FFMA2(acc[7], hk2, wd.y, acc[7]);
            }
            #pragma unroll
            for (int q = 0; q < 8; q++) {
                float lo, hi;
                UNPACK2(lo, hi, acc[q]);
                h2[qt * 16 + 2 * q + 0] = tanh_fast(lo);
                h2[qt * 16 + 2 * q + 1] = tanh_fast(hi);
            }
        }

        // ---- g_xz = CSCALE*(h2 @ Wx + b_rnn): f32x2, stored directly ----
        ulonglong2* op = (ulonglong2*)(g_xz + (size_t)t * 64);
        #pragma unroll
        for (int qt = 0; qt < 4; qt++) {
            unsigned long long acc[8];
            #pragma unroll
            for (int q = 0; q < 8; q++) acc[q] = sbrp[qt * 8 + q];
            #pragma unroll
            for (int k = 0; k < 64; k++) {
                unsigned long long hk2;
                PACK2(hk2, h2[k], h2[k]);
                const ulonglong2* wr =
                    (const ulonglong2*)(sWx + k * 64 + qt * 16);
                ulonglong2 wa = wr[0];
                FFMA2(acc[0], hk2, wa.x, acc[0]);
                FFMA2(acc[1], hk2, wa.y, acc[1]);
                ulonglong2 wb = wr[1];
                FFMA2(acc[2], hk2, wb.x, acc[2]);
                FFMA2(acc[3], hk2, wb.y, acc[3]);
                ulonglong2 wc = wr[2];
                FFMA2(acc[4], hk2, wc.x, acc[4]);
                FFMA2(acc[5], hk2, wc.y, acc[5]);
                ulonglong2 wd = wr[3];
                FFMA2(acc[6], hk2, wd.x, acc[6]);
                FFMA2(acc[7], hk2, wd.y, acc[7]);
            }
            #pragma unroll
            for (int i = 0; i < 4; i++) {
                ulonglong2 st;
                st.x = acc[2 * i];
                st.y = acc[2 * i + 1];
                op[qt * 4 + i] = st;
            }
        }
    }
}

// ---------------------------------------------------------------------------
// Kernel 2: single-warp chunked warm-start scan (W=64, L=128; 2048 chunks
// x 192 steps — same total work as R13, double the resident warps/SM).
// ---------------------------------------------------------------------------
#define SCAN_STEP(I, STORE)                                                   \
    {                                                                         \
        const int p = (I) & 1;                                                \
        const int s = (I) & (PF - 1);                                         \
        float zA = zqA[s], zB = zqB[s], m = mq[s];                            \
        zqA[s] = pf_z[0];                                                     \
        zqB[s] = pf_z[32];                                                    \
        mq[s]  = *pf_m;                                                       \
        pf_z += pf_ok ? 64 : 0;                                               \
        pf_m += pf_ok ? 1 : 0;                                                \
        pf_rem--;                                                             \
        pf_ok = pf_rem > 0;                                                   \
        float preA = fmaf(-m, 1.0f + hA, hA);                                 \
        float preB = fmaf(-m, 1.0f + hB, hB);                                 \
        float m2 = m + m;                                                     \
        unsigned long long zdA, zdB;                                          \
        PACK2(zdA, zA, 0.0f);                                                 \
        PACK2(zdB, zB, 0.0f);                                                 \
        const ulonglong2* hv = (const ulonglong2*)(&hbuf[p][0]);              \
        unsigned long long accA[8], accB[8];                                  \
        _Pragma("unroll")                                                     \
        for (int q = 0; q < 8; q++) {                                         \
            ulonglong2 ha = hv[q];                                            \
            ulonglong2 hb = hv[q + 8];                                        \
            if (q == 0) {                                                     \
                FFMA2(accA[0], ha.x, whA[0], zdA);                            \
                FFMA2(accB[0], ha.x, whB[0], zdB);                            \
            } else {                                                          \
                FMUL2(accA[q], ha.x, whA[2 * q]);                             \
                FMUL2(accB[q], ha.x, whB[2 * q]);                             \
            }                                                                 \
            FFMA2(accA[q], ha.y, whA[2 * q + 1], accA[q]);                    \
            FFMA2(accB[q], ha.y, whB[2 * q + 1], accB[q]);                    \
            FFMA2(accA[q], hb.x, whA[16 + 2 * q], accA[q]);                   \
            FFMA2(accB[q], hb.x, whB[16 + 2 * q], accB[q]);                   \
            FFMA2(accA[q], hb.y, whA[17 + 2 * q], accA[q]);                   \
            FFMA2(accB[q], hb.y, whB[17 + 2 * q], accB[q]);                   \
        }                                                                     \
        FADD2(accA[0], accA[0], accA[1]);                                     \
        FADD2(accA[2], accA[2], accA[3]);                                     \
        FADD2(accA[4], accA[4], accA[5]);                                     \
        FADD2(accA[6], accA[6], accA[7]);                                     \
        FADD2(accA[0], accA[0], accA[2]);                                     \
        FADD2(accA[4], accA[4], accA[6]);                                     \
        FADD2(accA[0], accA[0], accA[4]);                                     \
        FADD2(accB[0], accB[0], accB[1]);                                     \
        FADD2(accB[2], accB[2], accB[3]);                                     \
        FADD2(accB[4], accB[4], accB[5]);                                     \
        FADD2(accB[6], accB[6], accB[7]);                                     \
        FADD2(accB[0], accB[0], accB[2]);                                     \
        FADD2(accB[4], accB[4], accB[6]);                                     \
        FADD2(accB[0], accB[0], accB[4]);                                     \
        float loA, hiA, loB, hiB;                                             \
        UNPACK2(loA, hiA, accA[0]);                                           \
        UNPACK2(loB, hiB, accB[0]);                                           \
        float spA = loA + hiA;                                                \
        float spB = loB + hiB;                                                \
        float eA, eB;                                                         \
        asm("ex2.approx.f32 %0, %1;" : "=f"(eA) : "f"(spA));                  \
        asm("ex2.approx.f32 %0, %1;" : "=f"(eB) : "f"(spB));                  \
        float rA, rB;                                                         \
        asm("rcp.approx.f32 %0, %1;" : "=f"(rA) : "f"(eA + 1.0f));            \
        asm("rcp.approx.f32 %0, %1;" : "=f"(rB) : "f"(eB + 1.0f));            \
        hA = fmaf(m2, rA, preA);                                              \
        hB = fmaf(m2, rB, preB);                                              \
        if (STORE) {                                                          \
            st_p[0]  = hA;                                                    \
            st_p[32] = hB;                                                    \
            st_p += 64;                                                       \
        }                                                                     \
        hbuf[p ^ 1][j]      = hA;                                             \
        hbuf[p ^ 1][j + 32] = hB;                                             \
        __syncwarp();                                                         \
    }

__global__ void __launch_bounds__(32) chunk_scan_kernel(
    const float* __restrict__ Wh, int T)
{
    const int j = threadIdx.x;           // 0..31
    const int c = blockIdx.x;
    const int t_out0 = c * CHUNK_L;
    if (t_out0 >= T) return;
    const int t_out1 = min(t_out0 + CHUNK_L, T);
    const int t_start = max(0, t_out0 - WARMUP);

    unsigned long long whA[32], whB[32];
    #pragma unroll
    for (int i = 0; i < 32; i++) {
        float a0 = CSCALE * Wh[(2 * i) * 64 + j];
        float a1 = CSCALE * Wh[(2 * i + 1) * 64 + j];
        PACK2(whA[i], a0, a1);
        float b0 = CSCALE * Wh[(2 * i) * 64 + j + 32];
        float b1 = CSCALE * Wh[(2 * i + 1) * 64 + j + 32];
        PACK2(whB[i], b0, b1);
    }

    __shared__ __align__(16) float hbuf[2][64];
    hbuf[0][j] = 0.0f;
    hbuf[0][j + 32] = 0.0f;

    float zqA[PF], zqB[PF], mq[PF];
    #pragma unroll
    for (int s = 0; s < PF; s++) {
        int tt = t_start + s;
        int ttc = min(tt, t_out1 - 1);
        zqA[s] = g_xz[(size_t)ttc * 64 + j];
        zqB[s] = g_xz[(size_t)ttc * 64 + j + 32];
        mq[s]  = g_mask[ttc];
    }
    const int nsteps = t_out1 - t_start;
    int pf_rem = nsteps - PF;
    int pf_ok  = pf_rem > 0;
    int pf_t0  = min(t_start + PF, t_out1 - 1);
    const float* pf_z = g_xz + (size_t)pf_t0 * 64 + j;
    const float* pf_m = g_mask + pf_t0;
    float* st_p = g_hs + (size_t)t_out0 * 64 + j;
    __syncwarp();

    float hA = 0.0f, hB = 0.0f;
    const int nwarm = t_out0 - t_start;   // 0 or WARMUP (even)

    #pragma unroll 2
    for (int i = 0; i < nwarm; i++)
        SCAN_STEP(i, 0)

    #pragma unroll 2
    for (int i = nwarm; i < nsteps; i++)
        SCAN_STEP(i, 1)
}

// ---------------------------------------------------------------------------
// Kernel 3: means = hs @ Wm + bm.
// ---------------------------------------------------------------------------
__global__ void __launch_bounds__(256) means_kernel(
    const float* __restrict__ Wm, const float* __restrict__ bm,
    float4* __restrict__ out, int T)
{
    __shared__ __align__(16) float4 sWm[64];
    if (threadIdx.x < 64) sWm[threadIdx.x] = ((const float4*)Wm)[threadIdx.x];
    __syncthreads();
    float4 bmv = *(const float4*)bm;

    for (int t = blockIdx.x * 256 + threadIdx.x; t < T; t += gridDim.x * 256) {
        const float4* hr = (const float4*)(g_hs + (size_t)t * 64);
        float4 acc = bmv;
        #pragma unroll
        for (int q = 0; q < 16; q++) {
            float4 hv = hr[q];
            float4 w0 = sWm[4 * q + 0];
            float4 w1 = sWm[4 * q + 1];
            float4 w2 = sWm[4 * q + 2];
            float4 w3 = sWm[4 * q + 3];
            acc.x = fmaf(hv.x, w0.x, acc.x); acc.y = fmaf(hv.x, w0.y, acc.y);
            acc.z = fmaf(hv.x, w0.z, acc.z); acc.w = fmaf(hv.x, w0.w, acc.w);
            acc.x = fmaf(hv.y, w1.x, acc.x); acc.y = fmaf(hv.y, w1.y, acc.y);
            acc.z = fmaf(hv.y, w1.z, acc.z); acc.w = fmaf(hv.y, w1.w, acc.w);
            acc.x = fmaf(hv.z, w2.x, acc.x); acc.y = fmaf(hv.z, w2.y, acc.y);
            acc.z = fmaf(hv.z, w2.z, acc.z); acc.w = fmaf(hv.z, w2.w, acc.w);
            acc.x = fmaf(hv.w, w3.x, acc.x); acc.y = fmaf(hv.w, w3.y, acc.y);
            acc.z = fmaf(hv.w, w3.z, acc.z); acc.w = fmaf(hv.w, w3.w, acc.w);
        }
        out[t] = acc;
    }
}

// ---------------------------------------------------------------------------
extern "C" void kernel_launch(void* const* d_in, const int* in_sizes, int n_in,
                              void* d_out, int out_size)
{
    const float* x    = (const float*)d_in[0];
    const float* W1   = (const float*)d_in[1];
    const float* b1   = (const float*)d_in[2];
    const float* W2   = (const float*)d_in[3];
    const float* b2   = (const float*)d_in[4];
    const float* Wx   = (const float*)d_in[5];
    const float* Wh   = (const float*)d_in[6];
    const float* brnn = (const float*)d_in[7];
    const float* Wm   = (const float*)d_in[8];
    const float* bm   = (const float*)d_in[9];

    int T = in_sizes[0] / 8;   // x is [1, T, 8]
    if (T > MAX_T) T = MAX_T;

    int enc_blocks = (T + 127) / 128;
    if (enc_blocks > 2048) enc_blocks = 2048;

    int chunks = (T + CHUNK_L - 1) / CHUNK_L;   // 2048 for T=262144

    encoder_kernel<<<enc_blocks, 128>>>(x, W1, b1, W2, b2, Wx, brnn, T);
    chunk_scan_kernel<<<chunks, 32>>>(Wh, T);
    means_kernel<<<1024, 256>>>(Wm, bm, (float4*)d_out, T);
}

// round 15
// speedup vs baseline: 1.8902x; 1.8902x over previous
#include <cuda_runtime.h>
#include <cstdint>

// ---------------------------------------------------------------------------
// B=1, T=262144, D=8, H=64, A=4
//   mask = any(x != 0, -1); h1 = tanh(x@W1+b1); h2 = tanh(h1@W2+b2)
//   xz = h2@Wx + b_rnn;  h_t = mask ? tanh(xz_t + h_{t-1}@Wh) : h_{t-1}
//   means = hs@Wm + bm
// Inputs: x, W1, b1, W2, b2, Wx, Wh, b_rnn, Wm, bm.  Output: means [T,4] f32.
//
// R8-R13: warm-start chunked scan; single-warp scan CTA; branch-free step.
// R14: encoder f32x2 spilled again (reverted for good); 2x chunks no help.
// R15: THE FIX — the prefetch rings were dynamically indexed (s = i&3 under
//      partial unroll), so ptxas demoted them to LOCAL MEMORY: ~9 LDL/STL
//      per step was the hidden 6x per-step cost since R8. Step loop is now
//      unrolled in quads with compile-time ring slot and parity.
//
// CSCALE = -2*log2(e) folded into xz (encoder) and Wh (scan):
// tanh(s) = 2*rcp(ex2(CSCALE*s)+1) - 1; masked blend = one FMA:
// h' = fma(2m, r, h - m*(1+h)).
// ---------------------------------------------------------------------------

#define MAX_T 262144
#define H 64
#define CSCALE (-2.8853900817779268f)   /* -2*log2(e) */

#define CHUNK_L 256     /* output steps per chunk  */
#define WARMUP  128     /* warm-up steps per chunk */
#define PF 4            /* z/mask prefetch depth   */

__device__ float g_xz[MAX_T * H];    // holds CSCALE * (h2@Wx + b_rnn)
__device__ float g_mask[MAX_T];
__device__ float g_hs[MAX_T * H];

// Accurate fast tanh: e = exp(-2|v|); tanh = (1-e)/(1+e), signed.
__device__ __forceinline__ float tanh_fast(float v) {
    float a = fabsf(v) * CSCALE;
    float e;
    asm("ex2.approx.f32 %0, %1;" : "=f"(e) : "f"(a));
    float r;
    asm("rcp.approx.f32 %0, %1;" : "=f"(r) : "f"(e + 1.0f));
    return copysignf((1.0f - e) * r, v);
}

#define FFMA2(d, a, b, c) \
    asm("fma.rn.f32x2 %0, %1, %2, %3;" : "=l"(d) : "l"(a), "l"(b), "l"(c))
#define FMUL2(d, a, b) \
    asm("mul.rn.f32x2 %0, %1, %2;" : "=l"(d) : "l"(a), "l"(b))
#define FADD2(d, a, b) \
    asm("add.rn.f32x2 %0, %1, %2;" : "=l"(d) : "l"(a), "l"(b))
#define PACK2(d, lo, hi) \
    asm("mov.b64 %0, {%1, %2};" : "=l"(d) : "f"(lo), "f"(hi))
#define UNPACK2(lo, hi, s) \
    asm("mov.b64 {%0, %1}, %2;" : "=f"(lo), "=f"(hi) : "l"(s))

// ---------------------------------------------------------------------------
// Kernel 1: encoder (R9 scalar form — 168 regs, no spill, ~250us).
// ---------------------------------------------------------------------------
__global__ void __launch_bounds__(128, 3) encoder_kernel(
    const float* __restrict__ x,
    const float* __restrict__ W1, const float* __restrict__ b1,
    const float* __restrict__ W2, const float* __restrict__ b2,
    const float* __restrict__ Wx, const float* __restrict__ brnn,
    int T)
{
    __shared__ __align__(16) float sW1[8 * 64];
    __shared__ __align__(16) float sW2[64 * 64];
    __shared__ __align__(16) float sWx[64 * 64];
    __shared__ __align__(16) float sb1[64];
    __shared__ __align__(16) float sb2[64];
    __shared__ __align__(16) float sbr[64];

    for (int i = threadIdx.x; i < 8 * 64; i += 128) sW1[i] = W1[i];
    for (int i = threadIdx.x; i < 64 * 64; i += 128) { sW2[i] = W2[i]; sWx[i] = Wx[i]; }
    if (threadIdx.x < 64) {
        sb1[threadIdx.x] = b1[threadIdx.x];
        sb2[threadIdx.x] = b2[threadIdx.x];
        sbr[threadIdx.x] = brnn[threadIdx.x];
    }
    __syncthreads();

    const float4* sW1v = (const float4*)sW1;
    const float4* sW2v = (const float4*)sW2;
    const float4* sWxv = (const float4*)sWx;

    for (long t = (long)blockIdx.x * 128 + threadIdx.x; t < T;
         t += (long)gridDim.x * 128) {
        float4 xa = ((const float4*)x)[t * 2];
        float4 xb = ((const float4*)x)[t * 2 + 1];
        float xv[8] = {xa.x, xa.y, xa.z, xa.w, xb.x, xb.y, xb.z, xb.w};

        bool nz = (xa.x != 0.f) | (xa.y != 0.f) | (xa.z != 0.f) | (xa.w != 0.f) |
                  (xb.x != 0.f) | (xb.y != 0.f) | (xb.z != 0.f) | (xb.w != 0.f);
        g_mask[t] = nz ? 1.0f : 0.0f;

        // ---- h1 = tanh(x @ W1 + b1) ----
        float h1[64];
        {
            float4 acc[16];
            #pragma unroll
            for (int q = 0; q < 16; q++) acc[q] = ((const float4*)sb1)[q];
            #pragma unroll
            for (int d = 0; d < 8; d++) {
                float xd = xv[d];
                #pragma unroll
                for (int q = 0; q < 16; q++) {
                    float4 w = sW1v[d * 16 + q];
                    acc[q].x = fmaf(xd, w.x, acc[q].x);
                    acc[q].y = fmaf(xd, w.y, acc[q].y);
                    acc[q].z = fmaf(xd, w.z, acc[q].z);
                    acc[q].w = fmaf(xd, w.w, acc[q].w);
                }
            }
            #pragma unroll
            for (int q = 0; q < 16; q++) {
                h1[4 * q + 0] = tanh_fast(acc[q].x);
                h1[4 * q + 1] = tanh_fast(acc[q].y);
                h1[4 * q + 2] = tanh_fast(acc[q].z);
                h1[4 * q + 3] = tanh_fast(acc[q].w);
            }
        }

        // ---- h2 = tanh(h1 @ W2 + b2), four 16-wide quarters ----
        float h2[64];
        #pragma unroll
        for (int qt = 0; qt < 4; qt++) {
            float4 acc[4];
            #pragma unroll
            for (int q = 0; q < 4; q++) acc[q] = ((const float4*)sb2)[qt * 4 + q];
            #pragma unroll
            for (int k = 0; k < 64; k++) {
                float hk = h1[k];
                #pragma unroll
                for (int q = 0; q < 4; q++) {
                    float4 w = sW2v[k * 16 + qt * 4 + q];
                    acc[q].x = fmaf(hk, w.x, acc[q].x);
                    acc[q].y = fmaf(hk, w.y, acc[q].y);
                    acc[q].z = fmaf(hk, w.z, acc[q].z);
                    acc[q].w = fmaf(hk, w.w, acc[q].w);
                }
            }
            #pragma unroll
            for (int q = 0; q < 4; q++) {
                h2[qt * 16 + 4 * q + 0] = tanh_fast(acc[q].x);
                h2[qt * 16 + 4 * q + 1] = tanh_fast(acc[q].y);
                h2[qt * 16 + 4 * q + 2] = tanh_fast(acc[q].z);
                h2[qt * 16 + 4 * q + 3] = tanh_fast(acc[q].w);
            }
        }

        // ---- xz' = CSCALE * (h2 @ Wx + b_rnn), four 16-wide quarters ----
        float4* op = (float4*)(g_xz + (size_t)t * 64);
        #pragma unroll
        for (int qt = 0; qt < 4; qt++) {
            float4 acc[4];
            #pragma unroll
            for (int q = 0; q < 4; q++) acc[q] = ((const float4*)sbr)[qt * 4 + q];
            #pragma unroll
            for (int k = 0; k < 64; k++) {
                float hk = h2[k];
                #pragma unroll
                for (int q = 0; q < 4; q++) {
                    float4 w = sWxv[k * 16 + qt * 4 + q];
                    acc[q].x = fmaf(hk, w.x, acc[q].x);
                    acc[q].y = fmaf(hk, w.y, acc[q].y);
                    acc[q].z = fmaf(hk, w.z, acc[q].z);
                    acc[q].w = fmaf(hk, w.w, acc[q].w);
                }
            }
            #pragma unroll
            for (int q = 0; q < 4; q++) {
                acc[q].x *= CSCALE; acc[q].y *= CSCALE;
                acc[q].z *= CSCALE; acc[q].w *= CSCALE;
                op[qt * 4 + q] = acc[q];
            }
        }
    }
}

// ---------------------------------------------------------------------------
// Kernel 2: single-warp chunked warm-start scan (W=128, L=256; 1024 chunks).
// Step loop unrolled in QUADS: ring slot S_ (0..3) and buffer parity P_ (0/1)
// are compile-time, so zq/mq rings live in REGISTERS (no local memory).
// Requires nwarm and nsteps to be multiples of 4 (true for T=262144).
// ---------------------------------------------------------------------------
#define SCAN_STEP(S_, P_, STORE)                                              \
    {                                                                         \
        float zA = zqA[S_], zB = zqB[S_], m = mq[S_];                         \
        zqA[S_] = pf_z[0];                                                    \
        zqB[S_] = pf_z[32];                                                   \
        mq[S_]  = *pf_m;                                                      \
        pf_z += pf_ok ? 64 : 0;                                               \
        pf_m += pf_ok ? 1 : 0;                                                \
        pf_rem--;                                                             \
        pf_ok = pf_rem > 0;                                                   \
        float preA = fmaf(-m, 1.0f + hA, hA);                                 \
        float preB = fmaf(-m, 1.0f + hB, hB);                                 \
        float m2 = m + m;                                                     \
        unsigned long long zdA, zdB;                                          \
        PACK2(zdA, zA, 0.0f);                                                 \
        PACK2(zdB, zB, 0.0f);                                                 \
        const ulonglong2* hv = (const ulonglong2*)(&hbuf[P_][0]);             \
        unsigned long long accA[8], accB[8];                                  \
        _Pragma("unroll")                                                     \
        for (int q = 0; q < 8; q++) {                                         \
            ulonglong2 ha = hv[q];                                            \
            ulonglong2 hb = hv[q + 8];                                        \
            if (q == 0) {                                                     \
                FFMA2(accA[0], ha.x, whA[0], zdA);                            \
                FFMA2(accB[0], ha.x, whB[0], zdB);                            \
            } else {                                                          \
                FMUL2(accA[q], ha.x, whA[2 * q]);                             \
                FMUL2(accB[q], ha.x, whB[2 * q]);                             \
            }                                                                 \
            FFMA2(accA[q], ha.y, whA[2 * q + 1], accA[q]);                    \
            FFMA2(accB[q], ha.y, whB[2 * q + 1], accB[q]);                    \
            FFMA2(accA[q], hb.x, whA[16 + 2 * q], accA[q]);                   \
            FFMA2(accB[q], hb.x, whB[16 + 2 * q], accB[q]);                   \
            FFMA2(accA[q], hb.y, whA[17 + 2 * q], accA[q]);                   \
            FFMA2(accB[q], hb.y, whB[17 + 2 * q], accB[q]);                   \
        }                                                                     \
        FADD2(accA[0], accA[0], accA[1]);                                     \
        FADD2(accA[2], accA[2], accA[3]);                                     \
        FADD2(accA[4], accA[4], accA[5]);                                     \
        FADD2(accA[6], accA[6], accA[7]);                                     \
        FADD2(accA[0], accA[0], accA[2]);                                     \
        FADD2(accA[4], accA[4], accA[6]);                                     \
        FADD2(accA[0], accA[0], accA[4]);                                     \
        FADD2(accB[0], accB[0], accB[1]);                                     \
        FADD2(accB[2], accB[2], accB[3]);                                     \
        FADD2(accB[4], accB[4], accB[5]);                                     \
        FADD2(accB[6], accB[6], accB[7]);                                     \
        FADD2(accB[0], accB[0], accB[2]);                                     \
        FADD2(accB[4], accB[4], accB[6]);                                     \
        FADD2(accB[0], accB[0], accB[4]);                                     \
        float loA, hiA, loB, hiB;                                             \
        UNPACK2(loA, hiA, accA[0]);                                           \
        UNPACK2(loB, hiB, accB[0]);                                           \
        float spA = loA + hiA;                                                \
        float spB = loB + hiB;                                                \
        float eA, eB;                                                         \
        asm("ex2.approx.f32 %0, %1;" : "=f"(eA) : "f"(spA));                  \
        asm("ex2.approx.f32 %0, %1;" : "=f"(eB) : "f"(spB));                  \
        float rA, rB;                                                         \
        asm("rcp.approx.f32 %0, %1;" : "=f"(rA) : "f"(eA + 1.0f));            \
        asm("rcp.approx.f32 %0, %1;" : "=f"(rB) : "f"(eB + 1.0f));            \
        hA = fmaf(m2, rA, preA);                                              \
        hB = fmaf(m2, rB, preB);                                              \
        if (STORE) {                                                          \
            st_p[0]  = hA;                                                    \
            st_p[32] = hB;                                                    \
            st_p += 64;                                                       \
        }                                                                     \
        hbuf[(P_) ^ 1][j]      = hA;                                          \
        hbuf[(P_) ^ 1][j + 32] = hB;                                          \
        __syncwarp();                                                         \
    }

__global__ void __launch_bounds__(32) chunk_scan_kernel(
    const float* __restrict__ Wh, int T)
{
    const int j = threadIdx.x;           // 0..31
    const int c = blockIdx.x;
    const int t_out0 = c * CHUNK_L;
    if (t_out0 >= T) return;
    const int t_out1 = min(t_out0 + CHUNK_L, T);
    const int t_start = max(0, t_out0 - WARMUP);

    // Weight columns j (A) and j+32 (B), CSCALE-prescaled, packed along k.
    unsigned long long whA[32], whB[32];
    #pragma unroll
    for (int i = 0; i < 32; i++) {
        float a0 = CSCALE * Wh[(2 * i) * 64 + j];
        float a1 = CSCALE * Wh[(2 * i + 1) * 64 + j];
        PACK2(whA[i], a0, a1);
        float b0 = CSCALE * Wh[(2 * i) * 64 + j + 32];
        float b1 = CSCALE * Wh[(2 * i + 1) * 64 + j + 32];
        PACK2(whB[i], b0, b1);
    }

    __shared__ __align__(16) float hbuf[2][64];
    hbuf[0][j] = 0.0f;
    hbuf[0][j + 32] = 0.0f;

    // prefetch rings (STATIC indexing only) + rolling pointers
    float zqA[PF], zqB[PF], mq[PF];
    #pragma unroll
    for (int s = 0; s < PF; s++) {
        int ttc = min(t_start + s, t_out1 - 1);
        zqA[s] = g_xz[(size_t)ttc * 64 + j];
        zqB[s] = g_xz[(size_t)ttc * 64 + j + 32];
        mq[s]  = g_mask[ttc];
    }
    const int nsteps = t_out1 - t_start;     // multiple of 4 (256 or 384)
    int pf_rem = nsteps - PF;
    int pf_ok  = pf_rem > 0;
    int pf_t0  = min(t_start + PF, t_out1 - 1);
    const float* pf_z = g_xz + (size_t)pf_t0 * 64 + j;
    const float* pf_m = g_mask + pf_t0;
    float* st_p = g_hs + (size_t)t_out0 * 64 + j;
    __syncwarp();

    float hA = 0.0f, hB = 0.0f;
    const int nwarm = t_out0 - t_start;      // 0 or 128 — multiple of 4

    for (int i = 0; i < nwarm; i += 4) {
        SCAN_STEP(0, 0, 0)
        SCAN_STEP(1, 1, 0)
        SCAN_STEP(2, 0, 0)
        SCAN_STEP(3, 1, 0)
    }
    for (int i = nwarm; i < nsteps; i += 4) {
        SCAN_STEP(0, 0, 1)
        SCAN_STEP(1, 1, 1)
        SCAN_STEP(2, 0, 1)
        SCAN_STEP(3, 1, 1)
    }
}

// ---------------------------------------------------------------------------
// Kernel 3: means = hs @ Wm + bm.
// ---------------------------------------------------------------------------
__global__ void __launch_bounds__(256) means_kernel(
    const float* __restrict__ Wm, const float* __restrict__ bm,
    float4* __restrict__ out, int T)
{
    __shared__ __align__(16) float4 sWm[64];
    if (threadIdx.x < 64) sWm[threadIdx.x] = ((const float4*)Wm)[threadIdx.x];
    __syncthreads();
    float4 bmv = *(const float4*)bm;

    for (int t = blockIdx.x * 256 + threadIdx.x; t < T; t += gridDim.x * 256) {
        const float4* hr = (const float4*)(g_hs + (size_t)t * 64);
        float4 acc = bmv;
        #pragma unroll
        for (int q = 0; q < 16; q++) {
            float4 hv = hr[q];
            float4 w0 = sWm[4 * q + 0];
            float4 w1 = sWm[4 * q + 1];
            float4 w2 = sWm[4 * q + 2];
            float4 w3 = sWm[4 * q + 3];
            acc.x = fmaf(hv.x, w0.x, acc.x); acc.y = fmaf(hv.x, w0.y, acc.y);
            acc.z = fmaf(hv.x, w0.z, acc.z); acc.w = fmaf(hv.x, w0.w, acc.w);
            acc.x = fmaf(hv.y, w1.x, acc.x); acc.y = fmaf(hv.y, w1.y, acc.y);
            acc.z = fmaf(hv.y, w1.z, acc.z); acc.w = fmaf(hv.y, w1.w, acc.w);
            acc.x = fmaf(hv.z, w2.x, acc.x); acc.y = fmaf(hv.z, w2.y, acc.y);
            acc.z = fmaf(hv.z, w2.z, acc.z); acc.w = fmaf(hv.z, w2.w, acc.w);
            acc.x = fmaf(hv.w, w3.x, acc.x); acc.y = fmaf(hv.w, w3.y, acc.y);
            acc.z = fmaf(hv.w, w3.z, acc.z); acc.w = fmaf(hv.w, w3.w, acc.w);
        }
        out[t] = acc;
    }
}

// ---------------------------------------------------------------------------
extern "C" void kernel_launch(void* const* d_in, const int* in_sizes, int n_in,
                              void* d_out, int out_size)
{
    const float* x    = (const float*)d_in[0];
    const float* W1   = (const float*)d_in[1];
    const float* b1   = (const float*)d_in[2];
    const float* W2   = (const float*)d_in[3];
    const float* b2   = (const float*)d_in[4];
    const float* Wx   = (const float*)d_in[5];
    const float* Wh   = (const float*)d_in[6];
    const float* brnn = (const float*)d_in[7];
    const float* Wm   = (const float*)d_in[8];
    const float* bm   = (const float*)d_in[9];

    int T = in_sizes[0] / 8;   // x is [1, T, 8]
    if (T > MAX_T) T = MAX_T;

    int enc_blocks = (T + 127) / 128;
    if (enc_blocks > 2048) enc_blocks = 2048;

    int chunks = (T + CHUNK_L - 1) / CHUNK_L;   // 1024 for T=262144

    encoder_kernel<<<enc_blocks, 128>>>(x, W1, b1, W2, b2, Wx, brnn, T);
    chunk_scan_kernel<<<chunks, 32>>>(Wh, T);
    means_kernel<<<1024, 256>>>(Wm, bm, (float4*)d_out, T);
}